// round 12
// baseline (speedup 1.0000x reference)
#include <cuda_runtime.h>
#include <cstddef>

#define FULLMASK 0xffffffffu

// Global scratch (static __device__ arrays - no allocation at runtime)
static __device__ __align__(16) float g_patch[16384 * 784];   // 51.4 MB
static __device__ __align__(16) float g_tok2[16384 * 784];    // 51.4 MB (pair-permuted dim order)
static __device__ __align__(16) float g_v[16384 * 784];       // 51.4 MB stage1 V (pair-permuted)
static __device__ __align__(16) float g_v2[16384 * 392];      // 25.7 MB stage2 V
static __device__ unsigned g_ctrA;
static __device__ unsigned g_ctrB;

// ---------------------------------------------------------------------------
// Kernel P: grayscale + patch scatter, 4 pixels per thread + counter reset.
// ---------------------------------------------------------------------------
__global__ void vitP(const float* __restrict__ x)
{
    int t = blockIdx.x * 256 + threadIdx.x;
    if (t == 0) { g_ctrA = 0; g_ctrB = 0; }
    if (t >= 16384 * 196) return;
    int b = t / 196;
    int r = t - b * 196;          // py*7 + sx
    int py = r / 7;
    int sx = r - py * 7;
    const float4* xb = (const float4*)(x + (size_t)b * 2352);
    int off = py * 7 + sx;
    float4 c0 = __ldg(xb + off);
    float4 c1 = __ldg(xb + 196 + off);
    float4 c2 = __ldg(xb + 392 + off);
    float4 g;
    g.x = 0.299f * c0.x + 0.587f * c1.x + 0.114f * c2.x;
    g.y = 0.299f * c0.y + 0.587f * c1.y + 0.114f * c2.y;
    g.z = 0.299f * c0.z + 0.587f * c1.z + 0.114f * c2.z;
    g.w = 0.299f * c0.w + 0.587f * c1.w + 0.114f * c2.w;
    int patch = (py >> 2) * 7 + sx;
    *(float4*)(g_patch + (size_t)b * 784 + patch * 16 + (py & 3) * 4) = g;
}

// 16-FMA dot of patch quads p0..p3 against 4 weight quads, single accumulator
#define DOT16(acc, W0, W1, W2, W3)                                          \
    acc = fmaf(p0.x, W0.x, acc); acc = fmaf(p0.y, W0.y, acc);               \
    acc = fmaf(p0.z, W0.z, acc); acc = fmaf(p0.w, W0.w, acc);               \
    acc = fmaf(p1.x, W1.x, acc); acc = fmaf(p1.y, W1.y, acc);               \
    acc = fmaf(p1.z, W1.z, acc); acc = fmaf(p1.w, W1.w, acc);               \
    acc = fmaf(p2.x, W2.x, acc); acc = fmaf(p2.y, W2.y, acc);               \
    acc = fmaf(p2.z, W2.z, acc); acc = fmaf(p2.w, W2.w, acc);               \
    acc = fmaf(p3.x, W3.x, acc); acc = fmaf(p3.y, W3.y, acc);               \
    acc = fmaf(p3.z, W3.z, acc); acc = fmaf(p3.w, W3.w, acc);

// ---------------------------------------------------------------------------
// Kernel A (stage 1): octet = 1 element (4 per warp); lane (oct,d8) computes
// output dims d8 and d8+8. Weight LDS.128 = 128B broadcast x4 octets = 1 wf
// serving 4 elements. Pair-permuted v/tok2 layout (pos 2p+h <-> dim p+8h).
// Claim-ahead grain-1 work distribution. 448 threads, 1 CTA/SM.
// SMEM: 3*12544(W, [s][i4][half][d8][4]) + 3*784(bias pairs) + 14*128(kb)
//     = 41776 floats = 167104 B.
// ---------------------------------------------------------------------------
__global__ void __launch_bounds__(448, 1) vitA(
    const float* __restrict__ pe,
    const float* __restrict__ WQ1,
    const float* __restrict__ WK1,
    const float* __restrict__ WV1)
{
    extern __shared__ float sm[];
    float* sW = sm;           // 3 * 12544
    float* sBp = sm + 37632;  // 3 * 784, pair order
    float* sKV = sm + 39984;  // 14 warps * 128 (2 bufs * 4 oct * 16)

    const int tid = threadIdx.x;
    {
        const float* Wg[3] = {WQ1, WK1, WV1};
        for (int w = 0; w < 3; ++w) {
            const float* G = Wg[w];
            float* dst = sW + w * 12544;
            for (int idx = tid; idx < 12544; idx += 448) {
                int s = idx >> 8, r = idx & 255, i = r >> 4, o = r & 15;
                dst[s * 256 + (i >> 2) * 64 + (o >> 3) * 32 + (o & 7) * 4 + (i & 3)]
                    = G[(s * 16 + o) * 32 + i];
            }
            float* db = sBp + w * 784;
            for (int idx = tid; idx < 784; idx += 448) {
                int s = idx >> 4, o = idx & 15;
                const float* gw = G + (s * 16 + o) * 32 + 16;
                const float* pp = pe + s * 16;
                float acc = 0.f;
#pragma unroll
                for (int j = 0; j < 16; ++j) acc = fmaf(pp[j], gw[j], acc);
                db[s * 16 + (o & 7) * 2 + (o >> 3)] = acc;
            }
        }
    }
    __syncthreads();

    const int warpId = tid >> 5;
    const int lane = tid & 31;
    const int oct = lane >> 3;
    const int d8 = lane & 7;
    float* kb = sKV + warpId * 128;

    unsigned pcur;
    if ((lane & 7) == 0) pcur = atomicAdd(&g_ctrA, 1u);
    pcur = __shfl_sync(FULLMASK, pcur, oct << 3);

    while (!__all_sync(FULLMASK, pcur >= 16384u)) {
        unsigned pnraw = 0;
        if ((lane & 7) == 0) pnraw = atomicAdd(&g_ctrA, 1u);  // claim-ahead
        const bool valid = pcur < 16384u;
        const int elem = valid ? (int)pcur : 0;
        const float* pb = g_patch + (size_t)elem * 784;
        float* vb = g_v + (size_t)elem * 784;
        const float4* pv = (const float4*)pb;

        float S0[16], S1[16];
#pragma unroll
        for (int e = 0; e < 16; ++e) { S0[e] = 0.f; S1[e] = 0.f; }

        int cur = 0;
        float4 p0 = __ldg(pv + 0), p1 = __ldg(pv + 1);
        float4 p2 = __ldg(pv + 2), p3 = __ldg(pv + 3);

        // ---- pass 1: q,k,v (dims d8 & d8+8 per lane); gram; store v ----
#pragma unroll 1
        for (int s = 0; s < 49; ++s) {
            int sn = (s < 48) ? s + 1 : 48;
            float4 n0 = __ldg(pv + sn * 4 + 0), n1 = __ldg(pv + sn * 4 + 1);
            float4 n2 = __ldg(pv + sn * 4 + 2), n3 = __ldg(pv + sn * 4 + 3);

            const float* bq = sW + s * 256 + d8 * 4;
            const float* bk = bq + 12544;
            const float* bv = bq + 25088;
            float2 biq = *(const float2*)(sBp + s * 16 + d8 * 2);
            float2 bik = *(const float2*)(sBp + 784 + s * 16 + d8 * 2);
            float2 biv = *(const float2*)(sBp + 1568 + s * 16 + d8 * 2);

            float qlo = biq.x, qhi = biq.y;
            {
                float4 w0 = *(const float4*)(bq + 0),   w1 = *(const float4*)(bq + 64);
                float4 w2 = *(const float4*)(bq + 128), w3 = *(const float4*)(bq + 192);
                DOT16(qlo, w0, w1, w2, w3);
                float4 h0 = *(const float4*)(bq + 32),  h1 = *(const float4*)(bq + 96);
                float4 h2 = *(const float4*)(bq + 160), h3 = *(const float4*)(bq + 224);
                DOT16(qhi, h0, h1, h2, h3);
            }
            float klo = bik.x, khi = bik.y;
            {
                float4 w0 = *(const float4*)(bk + 0),   w1 = *(const float4*)(bk + 64);
                float4 w2 = *(const float4*)(bk + 128), w3 = *(const float4*)(bk + 192);
                DOT16(klo, w0, w1, w2, w3);
                float4 h0 = *(const float4*)(bk + 32),  h1 = *(const float4*)(bk + 96);
                float4 h2 = *(const float4*)(bk + 160), h3 = *(const float4*)(bk + 224);
                DOT16(khi, h0, h1, h2, h3);
            }
            float vlo = biv.x, vhi = biv.y;
            {
                float4 w0 = *(const float4*)(bv + 0),   w1 = *(const float4*)(bv + 64);
                float4 w2 = *(const float4*)(bv + 128), w3 = *(const float4*)(bv + 192);
                DOT16(vlo, w0, w1, w2, w3);
                float4 h0 = *(const float4*)(bv + 32),  h1 = *(const float4*)(bv + 96);
                float4 h2 = *(const float4*)(bv + 160), h3 = *(const float4*)(bv + 224);
                DOT16(vhi, h0, h1, h2, h3);
            }
            if (valid) *(float2*)(vb + s * 16 + d8 * 2) = make_float2(vlo, vhi);

            // share k within octet (pair order)
            *(float2*)(kb + cur * 64 + oct * 16 + d8 * 2) = make_float2(klo, khi);
            __syncwarp();
            const float4* kq = (const float4*)(kb + cur * 64 + oct * 16);
            float4 k0 = kq[0], k1 = kq[1], k2 = kq[2], k3 = kq[3];
            S0[0] = fmaf(qlo, k0.x, S0[0]);   S0[1] = fmaf(qlo, k0.y, S0[1]);
            S0[2] = fmaf(qlo, k0.z, S0[2]);   S0[3] = fmaf(qlo, k0.w, S0[3]);
            S0[4] = fmaf(qlo, k1.x, S0[4]);   S0[5] = fmaf(qlo, k1.y, S0[5]);
            S0[6] = fmaf(qlo, k1.z, S0[6]);   S0[7] = fmaf(qlo, k1.w, S0[7]);
            S0[8] = fmaf(qlo, k2.x, S0[8]);   S0[9] = fmaf(qlo, k2.y, S0[9]);
            S0[10] = fmaf(qlo, k2.z, S0[10]); S0[11] = fmaf(qlo, k2.w, S0[11]);
            S0[12] = fmaf(qlo, k3.x, S0[12]); S0[13] = fmaf(qlo, k3.y, S0[13]);
            S0[14] = fmaf(qlo, k3.z, S0[14]); S0[15] = fmaf(qlo, k3.w, S0[15]);
            S1[0] = fmaf(qhi, k0.x, S1[0]);   S1[1] = fmaf(qhi, k0.y, S1[1]);
            S1[2] = fmaf(qhi, k0.z, S1[2]);   S1[3] = fmaf(qhi, k0.w, S1[3]);
            S1[4] = fmaf(qhi, k1.x, S1[4]);   S1[5] = fmaf(qhi, k1.y, S1[5]);
            S1[6] = fmaf(qhi, k1.z, S1[6]);   S1[7] = fmaf(qhi, k1.w, S1[7]);
            S1[8] = fmaf(qhi, k2.x, S1[8]);   S1[9] = fmaf(qhi, k2.y, S1[9]);
            S1[10] = fmaf(qhi, k2.z, S1[10]); S1[11] = fmaf(qhi, k2.w, S1[11]);
            S1[12] = fmaf(qhi, k3.x, S1[12]); S1[13] = fmaf(qhi, k3.y, S1[13]);
            S1[14] = fmaf(qhi, k3.z, S1[14]); S1[15] = fmaf(qhi, k3.w, S1[15]);
            cur ^= 1;
            p0 = n0; p1 = n1; p2 = n2; p3 = n3;
        }
#pragma unroll
        for (int e = 0; e < 16; ++e) { S0[e] *= (1.f / 7.f); S1[e] *= (1.f / 7.f); }

        __syncwarp();  // v stores visible to octet lanes

        // ---- pass 2: read v (pair order), apply S, softmax(16) -> tok2 ----
        float* ob = g_tok2 + (size_t)elem * 784;
        const float4* vv = (const float4*)vb;
        float4 u0 = vv[0], u1 = vv[1], u2 = vv[2], u3 = vv[3];
#pragma unroll 1
        for (int s = 0; s < 49; ++s) {
            int sn = (s < 48) ? s + 1 : 48;
            float4 m0 = vv[sn * 4 + 0], m1 = vv[sn * 4 + 1];
            float4 m2 = vv[sn * 4 + 2], m3 = vv[sn * 4 + 3];

            float oa = 0.f, ob2 = 0.f, ha = 0.f, hb2 = 0.f;
            oa = fmaf(S0[0], u0.x, oa);   ob2 = fmaf(S0[1], u0.y, ob2);
            oa = fmaf(S0[2], u0.z, oa);   ob2 = fmaf(S0[3], u0.w, ob2);
            oa = fmaf(S0[4], u1.x, oa);   ob2 = fmaf(S0[5], u1.y, ob2);
            oa = fmaf(S0[6], u1.z, oa);   ob2 = fmaf(S0[7], u1.w, ob2);
            oa = fmaf(S0[8], u2.x, oa);   ob2 = fmaf(S0[9], u2.y, ob2);
            oa = fmaf(S0[10], u2.z, oa);  ob2 = fmaf(S0[11], u2.w, ob2);
            oa = fmaf(S0[12], u3.x, oa);  ob2 = fmaf(S0[13], u3.y, ob2);
            oa = fmaf(S0[14], u3.z, oa);  ob2 = fmaf(S0[15], u3.w, ob2);
            ha = fmaf(S1[0], u0.x, ha);   hb2 = fmaf(S1[1], u0.y, hb2);
            ha = fmaf(S1[2], u0.z, ha);   hb2 = fmaf(S1[3], u0.w, hb2);
            ha = fmaf(S1[4], u1.x, ha);   hb2 = fmaf(S1[5], u1.y, hb2);
            ha = fmaf(S1[6], u1.z, ha);   hb2 = fmaf(S1[7], u1.w, hb2);
            ha = fmaf(S1[8], u2.x, ha);   hb2 = fmaf(S1[9], u2.y, hb2);
            ha = fmaf(S1[10], u2.z, ha);  hb2 = fmaf(S1[11], u2.w, hb2);
            ha = fmaf(S1[12], u3.x, ha);  hb2 = fmaf(S1[13], u3.y, hb2);
            ha = fmaf(S1[14], u3.z, ha);  hb2 = fmaf(S1[15], u3.w, hb2);
            float olo = oa + ob2;
            float ohi = ha + hb2;

            float mx = fmaxf(olo, ohi);
#pragma unroll
            for (int dd = 4; dd; dd >>= 1)
                mx = fmaxf(mx, __shfl_xor_sync(FULLMASK, mx, dd, 8));
            float elo = __expf(olo - mx);
            float ehi = __expf(ohi - mx);
            float su = elo + ehi;
#pragma unroll
            for (int dd = 4; dd; dd >>= 1)
                su += __shfl_xor_sync(FULLMASK, su, dd, 8);
            float inv = __fdividef(1.f, su);
            if (valid) *(float2*)(ob + s * 16 + d8 * 2) = make_float2(elo * inv, ehi * inv);
            u0 = m0; u1 = m1; u2 = m2; u3 = m3;
        }

        pcur = __shfl_sync(FULLMASK, pnraw, oct << 3);
    }
}

// ---------------------------------------------------------------------------
// Kernel B: QKV2 weights in SMEM (i-permuted for pair-order tok2) -> attn(8)
// -> softmax -> fc1 fused -> octet butterfly -> relu -> fc2 -> out.
// Octet = 1 element, claim-ahead grain-1. 448 threads, 2 CTAs/SM, grid 296.
// SMEM: 3*6272 + 6272 + 160 + 32 + 14*64(kv) + 14*64(hb) = 27072 fl = 108288 B.
// ---------------------------------------------------------------------------
__global__ void __launch_bounds__(448, 2) vitB(
    const float* __restrict__ WQ2,
    const float* __restrict__ WK2,
    const float* __restrict__ WV2,
    const float* __restrict__ f1w,
    const float* __restrict__ f1b,
    const float* __restrict__ f2w,
    const float* __restrict__ f2b,
    float* __restrict__ out)
{
    extern __shared__ float sm[];
    float* sW2 = sm;            // Q 0, K 6272, V 12544
    float* sF1t = sm + 18816;   // 6272 : [d8][s][j]
    float* sF2 = sm + 25088;    // 160
    float* sB1 = sm + 25248;    // 16
    float* sB2 = sm + 25264;    // 16
    float* sKV = sm + 25280;    // 14 * 64
    float* sHB = sm + 26176;    // 14 * 64

    const int tid = threadIdx.x;
    {
        const float* Wg[3] = {WQ2, WK2, WV2};
        for (int w = 0; w < 3; ++w) {
            const float* G = Wg[w];
            float* dst = sW2 + w * 6272;
            for (int idx = tid; idx < 6272; idx += 448) {
                int s = idx >> 7, r = idx & 127, m = r >> 3, d = r & 7;
                int il = (m >> 1) | ((m & 1) << 3);  // pair-permuted tok2 order
                dst[s * 128 + (m >> 2) * 32 + d * 4 + (m & 3)] = G[(s * 8 + d) * 16 + il];
            }
        }
        for (int idx = tid; idx < 6272; idx += 448) {
            int d = idx / 784, r = idx - d * 784, s = r >> 4, j = r & 15;
            sF1t[(d * 49 + s) * 16 + j] = f1w[j * 392 + s * 8 + d];
        }
        for (int idx = tid; idx < 160; idx += 448) {
            int j = idx / 10, c = idx - j * 10;
            sF2[idx] = f2w[c * 16 + j];
        }
        if (tid < 16) sB1[tid] = f1b[tid];
        if (tid < 10) sB2[tid] = f2b[tid];
    }
    __syncthreads();

    const int warpId = tid >> 5;
    const int lane = tid & 31;
    const int oct = lane >> 3;
    const int d8 = lane & 7;
    float* kb = sKV + warpId * 64;
    float* hb = sHB + warpId * 64;

    unsigned pcur;
    if ((lane & 7) == 0) pcur = atomicAdd(&g_ctrB, 1u);
    pcur = __shfl_sync(FULLMASK, pcur, oct << 3);

    while (!__all_sync(FULLMASK, pcur >= 16384u)) {
        unsigned pnraw = 0;
        if ((lane & 7) == 0) pnraw = atomicAdd(&g_ctrB, 1u);  // claim-ahead
        const bool valid = pcur < 16384u;
        const int elem = valid ? (int)pcur : 0;
        const float* tb = g_tok2 + (size_t)elem * 784;
        float* vb = g_v2 + (size_t)elem * 392;

        float S2[8];
#pragma unroll
        for (int e = 0; e < 8; ++e) S2[e] = 0.f;

        int cur = 0;
        const float4* pv = (const float4*)tb;

        // ---- pass 1: q2,k2,v2 per s; gram; store v2 ----
#pragma unroll 1
        for (int s = 0; s < 49; ++s) {
            float4 p0 = __ldg(pv + s * 4 + 0), p1 = __ldg(pv + s * 4 + 1);
            float4 p2 = __ldg(pv + s * 4 + 2), p3 = __ldg(pv + s * 4 + 3);

            const float* bq = sW2 + s * 128 + d8 * 4;
            float4 a0 = *(const float4*)(bq + 0),  a1 = *(const float4*)(bq + 32);
            float4 a2 = *(const float4*)(bq + 64), a3 = *(const float4*)(bq + 96);
            float q0 = 0.f;
            DOT16(q0, a0, a1, a2, a3);

            const float* bk = bq + 6272;
            float4 b0 = *(const float4*)(bk + 0),  b1 = *(const float4*)(bk + 32);
            float4 b2 = *(const float4*)(bk + 64), b3 = *(const float4*)(bk + 96);
            float k0 = 0.f;
            DOT16(k0, b0, b1, b2, b3);

            const float* bv = bq + 12544;
            float4 c0 = *(const float4*)(bv + 0),  c1 = *(const float4*)(bv + 32);
            float4 c2 = *(const float4*)(bv + 64), c3 = *(const float4*)(bv + 96);
            float w0 = 0.f;
            DOT16(w0, c0, c1, c2, c3);
            if (valid) vb[s * 8 + d8] = w0;   // store v2

            kb[cur * 32 + lane] = k0;
            __syncwarp();
            const float4* kv4 = (const float4*)(kb + cur * 32 + oct * 8);
            float4 v0 = kv4[0], v1 = kv4[1];
            S2[0] = fmaf(q0, v0.x, S2[0]); S2[1] = fmaf(q0, v0.y, S2[1]);
            S2[2] = fmaf(q0, v0.z, S2[2]); S2[3] = fmaf(q0, v0.w, S2[3]);
            S2[4] = fmaf(q0, v1.x, S2[4]); S2[5] = fmaf(q0, v1.y, S2[5]);
            S2[6] = fmaf(q0, v1.z, S2[6]); S2[7] = fmaf(q0, v1.w, S2[7]);
            cur ^= 1;
        }
#pragma unroll
        for (int e = 0; e < 8; ++e) S2[e] *= (1.f / 7.f);

        __syncwarp();  // v2 stores visible

        // ---- pass 2: read v2, apply S2, softmax(8), fc1 fused ----
        float h[16];
#pragma unroll
        for (int j = 0; j < 16; ++j) h[j] = 0.f;

        const float4* vv = (const float4*)vb;
#pragma unroll 1
        for (int s = 0; s < 49; ++s) {
            float4 u0 = vv[s * 2 + 0], u1 = vv[s * 2 + 1];

            float o = 0.f;
            o = fmaf(S2[0], u0.x, o); o = fmaf(S2[1], u0.y, o);
            o = fmaf(S2[2], u0.z, o); o = fmaf(S2[3], u0.w, o);
            o = fmaf(S2[4], u1.x, o); o = fmaf(S2[5], u1.y, o);
            o = fmaf(S2[6], u1.z, o); o = fmaf(S2[7], u1.w, o);

            float m = o;
#pragma unroll
            for (int dd = 4; dd; dd >>= 1)
                m = fmaxf(m, __shfl_xor_sync(FULLMASK, m, dd, 8));
            float ex = __expf(o - m);
            float su = ex;
#pragma unroll
            for (int dd = 4; dd; dd >>= 1)
                su += __shfl_xor_sync(FULLMASK, su, dd, 8);
            float tv = __fdividef(ex, su);   // tok3[s][d8]

            const float4* wt = (const float4*)(sF1t + (d8 * 49 + s) * 16);
            float4 f0 = wt[0], f1 = wt[1], f2 = wt[2], f3 = wt[3];
            h[0] = fmaf(tv, f0.x, h[0]);  h[1] = fmaf(tv, f0.y, h[1]);
            h[2] = fmaf(tv, f0.z, h[2]);  h[3] = fmaf(tv, f0.w, h[3]);
            h[4] = fmaf(tv, f1.x, h[4]);  h[5] = fmaf(tv, f1.y, h[5]);
            h[6] = fmaf(tv, f1.z, h[6]);  h[7] = fmaf(tv, f1.w, h[7]);
            h[8] = fmaf(tv, f2.x, h[8]);  h[9] = fmaf(tv, f2.y, h[9]);
            h[10] = fmaf(tv, f2.z, h[10]); h[11] = fmaf(tv, f2.w, h[11]);
            h[12] = fmaf(tv, f3.x, h[12]); h[13] = fmaf(tv, f3.y, h[13]);
            h[14] = fmaf(tv, f3.z, h[14]); h[15] = fmaf(tv, f3.w, h[15]);
        }

        // split-butterfly reduce over the 8 octet lanes: 14 shfl total
#pragma unroll
        for (int j = 0; j < 8; ++j) {
            float sendv = (d8 & 1) ? h[j] : h[j + 8];
            float keep  = (d8 & 1) ? h[j + 8] : h[j];
            h[j] = keep + __shfl_xor_sync(FULLMASK, sendv, 1, 8);
        }
#pragma unroll
        for (int j = 0; j < 4; ++j) {
            float sendv = (d8 & 2) ? h[j] : h[j + 4];
            float keep  = (d8 & 2) ? h[j + 4] : h[j];
            h[j] = keep + __shfl_xor_sync(FULLMASK, sendv, 2, 8);
        }
#pragma unroll
        for (int j = 0; j < 2; ++j) {
            float sendv = (d8 & 4) ? h[j] : h[j + 2];
            float keep  = (d8 & 4) ? h[j + 2] : h[j];
            h[j] = keep + __shfl_xor_sync(FULLMASK, sendv, 4, 8);
        }
        int ja = 8 * (d8 & 1) + 4 * ((d8 >> 1) & 1) + 2 * ((d8 >> 2) & 1);
        __syncwarp();
        hb[oct * 16 + ja] = fmaxf(h[0] + sB1[ja], 0.f);
        hb[oct * 16 + ja + 1] = fmaxf(h[1] + sB1[ja + 1], 0.f);
        __syncwarp();

        // ---- fc2 + softmax over 10 (octet-local) ----
        const float* ho = hb + oct * 16;
        int c2 = (d8 < 2) ? (d8 + 8) : 8;
        float lg1 = sB2[d8];
        float lg2 = sB2[c2];
#pragma unroll
        for (int j = 0; j < 16; ++j) {
            float hv = ho[j];
            lg1 = fmaf(hv, sF2[j * 10 + d8], lg1);
            lg2 = fmaf(hv, sF2[j * 10 + c2], lg2);
        }
        float lg2v = (d8 < 2) ? lg2 : -1e30f;
        float m = fmaxf(lg1, lg2v);
#pragma unroll
        for (int dd = 4; dd; dd >>= 1)
            m = fmaxf(m, __shfl_xor_sync(FULLMASK, m, dd, 8));
        float e1 = __expf(lg1 - m);
        float e2 = (d8 < 2) ? __expf(lg2 - m) : 0.f;
        float su = e1 + e2;
#pragma unroll
        for (int dd = 4; dd; dd >>= 1)
            su += __shfl_xor_sync(FULLMASK, su, dd, 8);
        float inv = __fdividef(1.f, su);
        if (valid) {
            out[elem * 10 + d8] = e1 * inv;
            if (d8 < 2) out[elem * 10 + 8 + d8] = e2 * inv;
        }
        __syncwarp();  // protect hb before next iteration

        pcur = __shfl_sync(FULLMASK, pnraw, oct << 3);
    }
}

extern "C" void kernel_launch(void* const* d_in, const int* in_sizes, int n_in,
                              void* d_out, int out_size)
{
    (void)in_sizes; (void)n_in; (void)out_size;
    const float* x   = (const float*)d_in[0];
    const float* pe  = (const float*)d_in[1];
    const float* WQ1 = (const float*)d_in[2];
    const float* WK1 = (const float*)d_in[3];
    const float* WV1 = (const float*)d_in[4];
    const float* WQ2 = (const float*)d_in[5];
    const float* WK2 = (const float*)d_in[6];
    const float* WV2 = (const float*)d_in[7];
    const float* f1w = (const float*)d_in[8];
    const float* f1b = (const float*)d_in[9];
    const float* f2w = (const float*)d_in[10];
    const float* f2b = (const float*)d_in[11];
    float* out = (float*)d_out;

    const size_t smA = (size_t)41776 * sizeof(float);  // 167104 B
    const size_t smB = (size_t)27072 * sizeof(float);  // 108288 B
    cudaFuncSetAttribute(vitA, cudaFuncAttributeMaxDynamicSharedMemorySize, (int)smA);
    cudaFuncSetAttribute(vitB, cudaFuncAttributeMaxDynamicSharedMemorySize, (int)smB);

    vitP<<<(16384 * 196 + 255) / 256, 256>>>(x);
    vitA<<<148, 448, smA>>>(pe, WQ1, WK1, WV1);
    vitB<<<296, 448, smB>>>(WQ2, WK2, WV2, f1w, f1b, f2w, f2b, out);
}

// round 13
// speedup vs baseline: 1.1302x; 1.1302x over previous
#include <cuda_runtime.h>
#include <cstddef>

#define FULLMASK 0xffffffffu
typedef unsigned long long u64;

// f32x2 packed helpers (sm_103a packed fp32 pipe; 2 FMAs per instruction)
__device__ __forceinline__ u64 ffma2(u64 a, u64 b, u64 c) {
    u64 d; asm("fma.rn.f32x2 %0, %1, %2, %3;" : "=l"(d) : "l"(a), "l"(b), "l"(c)); return d;
}
__device__ __forceinline__ u64 fadd2(u64 a, u64 b) {
    u64 d; asm("add.rn.f32x2 %0, %1, %2;" : "=l"(d) : "l"(a), "l"(b)); return d;
}
__device__ __forceinline__ u64 fmul2(u64 a, u64 b) {
    u64 d; asm("mul.rn.f32x2 %0, %1, %2;" : "=l"(d) : "l"(a), "l"(b)); return d;
}
__device__ __forceinline__ u64 pack2(float lo, float hi) {
    u64 d; asm("mov.b64 %0, {%1, %2};" : "=l"(d) : "f"(lo), "f"(hi)); return d;
}
__device__ __forceinline__ float2 unpack2(u64 a) {
    float2 r; asm("mov.b64 {%0, %1}, %2;" : "=f"(r.x), "=f"(r.y) : "l"(a)); return r;
}

// Global scratch (static __device__ arrays - no allocation at runtime)
static __device__ __align__(16) float g_patch[16384 * 784];   // 51.4 MB
static __device__ __align__(16) float g_tok2[16384 * 784];    // 51.4 MB
static __device__ __align__(16) float g_v[16384 * 784];       // 51.4 MB stage1 V
static __device__ __align__(16) float g_v2[16384 * 392];      // 25.7 MB stage2 V
static __device__ unsigned g_ctrA;
static __device__ unsigned g_ctrB;

// ---------------------------------------------------------------------------
// Kernel P: grayscale + patch scatter, 4 pixels per thread + counter reset.
// ---------------------------------------------------------------------------
__global__ void vitP(const float* __restrict__ x)
{
    int t = blockIdx.x * 256 + threadIdx.x;
    if (t == 0) { g_ctrA = 0; g_ctrB = 0; }
    if (t >= 16384 * 196) return;
    int b = t / 196;
    int r = t - b * 196;          // py*7 + sx
    int py = r / 7;
    int sx = r - py * 7;
    const float4* xb = (const float4*)(x + (size_t)b * 2352);
    int off = py * 7 + sx;
    float4 c0 = __ldg(xb + off);
    float4 c1 = __ldg(xb + 196 + off);
    float4 c2 = __ldg(xb + 392 + off);
    float4 g;
    g.x = 0.299f * c0.x + 0.587f * c1.x + 0.114f * c2.x;
    g.y = 0.299f * c0.y + 0.587f * c1.y + 0.114f * c2.y;
    g.z = 0.299f * c0.z + 0.587f * c1.z + 0.114f * c2.z;
    g.w = 0.299f * c0.w + 0.587f * c1.w + 0.114f * c2.w;
    int patch = (py >> 2) * 7 + sx;
    *(float4*)(g_patch + (size_t)b * 784 + patch * 16 + (py & 3) * 4) = g;
}

// Packed 16-dot: P0..P7 (u64 pairs of the 16 inputs) against a SMEM weight
// block with quad stride QS ulonglong2's; result = scalar + bias.
#define PDOT(res, base, qs, bias) {                                          \
    const ulonglong2* _w = (const ulonglong2*)(base);                        \
    ulonglong2 _w0 = _w[0], _w1 = _w[qs], _w2 = _w[2*(qs)], _w3 = _w[3*(qs)];\
    u64 _a = 0ull, _b = 0ull;                                                \
    _a = ffma2(P0, _w0.x, _a); _b = ffma2(P1, _w0.y, _b);                    \
    _a = ffma2(P2, _w1.x, _a); _b = ffma2(P3, _w1.y, _b);                    \
    _a = ffma2(P4, _w2.x, _a); _b = ffma2(P5, _w2.y, _b);                    \
    _a = ffma2(P6, _w3.x, _a); _b = ffma2(P7, _w3.y, _b);                    \
    float2 _f = unpack2(fadd2(_a, _b));                                      \
    res = _f.x + _f.y + (bias); }

// ---------------------------------------------------------------------------
// Kernel A (stage 1): single-pass QKV (packed f32x2 math) -> gram S (k via
// SMEM broadcast) -> v to g_v. Pass 2: v back (prefetched), apply S,
// softmax(16) -> tok2. Warp = 2 half-warps = 2 elements. 640 threads.
// SMEM: 3*12544 + 3*784 + 20*64 = 41264 floats = 165056 B.
// ---------------------------------------------------------------------------
__global__ void __launch_bounds__(640, 1) vitA(
    const float* __restrict__ pe,
    const float* __restrict__ WQ1,
    const float* __restrict__ WK1,
    const float* __restrict__ WV1)
{
    extern __shared__ float sm[];
    float* sW = sm;          // 3 * 12544, layout [w][s][i/4][o][4]
    float* sB = sm + 37632;  // 3 * 784
    float* sKV = sm + 39984; // 20 warps * 64

    const int tid = threadIdx.x;
    {
        const float* Wg[3] = {WQ1, WK1, WV1};
        for (int w = 0; w < 3; ++w) {
            const float* G = Wg[w];
            float* dst = sW + w * 12544;
            for (int idx = tid; idx < 12544; idx += 640) {
                int s = idx >> 8, r = idx & 255, i = r >> 4, o = r & 15;
                dst[s * 256 + (i >> 2) * 64 + o * 4 + (i & 3)] = G[(s * 16 + o) * 32 + i];
            }
            float* db = sB + w * 784;
            for (int idx = tid; idx < 784; idx += 640) {
                int s = idx >> 4, o = idx & 15;
                const float* gw = G + (s * 16 + o) * 32 + 16;
                const float* pp = pe + s * 16;
                float acc = 0.f;
#pragma unroll
                for (int j = 0; j < 16; ++j) acc = fmaf(pp[j], gw[j], acc);
                db[idx] = acc;
            }
        }
    }
    __syncthreads();

    const int warpId = tid >> 5;
    const int lane = tid & 31;
    const int hh = lane >> 4;
    const int l16 = lane & 15;
    float* kb = sKV + warpId * 64;   // [buf 0/1][lane]

    for (;;) {
        unsigned p;
        if (lane == 0) p = atomicAdd(&g_ctrA, 1u);
        p = __shfl_sync(FULLMASK, p, 0);
        if (p >= 8192) break;
        const int elem = (int)p * 2 + hh;
        const float* pb = g_patch + (size_t)elem * 784;
        float* vb = g_v + (size_t)elem * 784;
        const ulonglong2* pvu = (const ulonglong2*)pb;

        u64 Sp[8];
#pragma unroll
        for (int e = 0; e < 8; ++e) Sp[e] = 0ull;

        int cur = 0;
        ulonglong2 t0 = __ldg(pvu + 0), t1 = __ldg(pvu + 1);
        ulonglong2 t2 = __ldg(pvu + 2), t3 = __ldg(pvu + 3);
        u64 P0 = t0.x, P1 = t0.y, P2 = t1.x, P3 = t1.y;
        u64 P4 = t2.x, P5 = t2.y, P6 = t3.x, P7 = t3.y;

        // ---- pass 1: q,k,v per s; gram S; store v ----
#pragma unroll 1
        for (int s = 0; s < 49; ++s) {
            int sn = (s < 48) ? s + 1 : 48;
            ulonglong2 n0 = __ldg(pvu + sn * 4 + 0), n1 = __ldg(pvu + sn * 4 + 1);
            ulonglong2 n2 = __ldg(pvu + sn * 4 + 2), n3 = __ldg(pvu + sn * 4 + 3);

            float q, k, v;
            PDOT(q, sW + s * 256 + l16 * 4, 8, sB[s * 16 + l16]);
            PDOT(k, sW + 12544 + s * 256 + l16 * 4, 8, sB[784 + s * 16 + l16]);
            PDOT(v, sW + 25088 + s * 256 + l16 * 4, 8, sB[1568 + s * 16 + l16]);
            vb[s * 16 + l16] = v;

            kb[cur * 32 + lane] = k;
            __syncwarp();
            const ulonglong2* kq = (const ulonglong2*)(kb + cur * 32 + hh * 16);
            ulonglong2 K0 = kq[0], K1 = kq[1], K2 = kq[2], K3 = kq[3];
            u64 qp = pack2(q, q);
            Sp[0] = ffma2(qp, K0.x, Sp[0]); Sp[1] = ffma2(qp, K0.y, Sp[1]);
            Sp[2] = ffma2(qp, K1.x, Sp[2]); Sp[3] = ffma2(qp, K1.y, Sp[3]);
            Sp[4] = ffma2(qp, K2.x, Sp[4]); Sp[5] = ffma2(qp, K2.y, Sp[5]);
            Sp[6] = ffma2(qp, K3.x, Sp[6]); Sp[7] = ffma2(qp, K3.y, Sp[7]);
            cur ^= 1;
            P0 = n0.x; P1 = n0.y; P2 = n1.x; P3 = n1.y;
            P4 = n2.x; P5 = n2.y; P6 = n3.x; P7 = n3.y;
        }
        {
            u64 sv = pack2(1.f / 7.f, 1.f / 7.f);
#pragma unroll
            for (int e = 0; e < 8; ++e) Sp[e] = fmul2(Sp[e], sv);
        }

        __syncwarp();  // v stores visible to all lanes of the warp

        // ---- pass 2: read v, apply S, softmax(16) -> tok2 ----
        float* ob = g_tok2 + (size_t)elem * 784;
        const ulonglong2* vvu = (const ulonglong2*)vb;
        ulonglong2 U0 = vvu[0], U1 = vvu[1], U2 = vvu[2], U3 = vvu[3];
#pragma unroll 1
        for (int s = 0; s < 49; ++s) {
            int sn = (s < 48) ? s + 1 : 48;
            ulonglong2 M0 = vvu[sn * 4 + 0], M1 = vvu[sn * 4 + 1];
            ulonglong2 M2 = vvu[sn * 4 + 2], M3 = vvu[sn * 4 + 3];

            u64 a = 0ull, b = 0ull;
            a = ffma2(Sp[0], U0.x, a); b = ffma2(Sp[1], U0.y, b);
            a = ffma2(Sp[2], U1.x, a); b = ffma2(Sp[3], U1.y, b);
            a = ffma2(Sp[4], U2.x, a); b = ffma2(Sp[5], U2.y, b);
            a = ffma2(Sp[6], U3.x, a); b = ffma2(Sp[7], U3.y, b);
            float2 f = unpack2(fadd2(a, b));
            float o = f.x + f.y;

            float m = o;
#pragma unroll
            for (int dd = 8; dd; dd >>= 1)
                m = fmaxf(m, __shfl_xor_sync(FULLMASK, m, dd, 16));
            float ex = __expf(o - m);
            float sum = ex;
#pragma unroll
            for (int dd = 8; dd; dd >>= 1)
                sum += __shfl_xor_sync(FULLMASK, sum, dd, 16);
            ob[s * 16 + l16] = __fdividef(ex, sum);
            U0 = M0; U1 = M1; U2 = M2; U3 = M3;
        }
    }
}

// ---------------------------------------------------------------------------
// Kernel B: tok2 -> QKV2 (packed) -> attn(8) -> softmax -> fc1 fused (packed)
// -> octet butterfly -> relu -> fc2 -> out. Warp = 4 octets = 4 elements.
// 640 threads. SMEM: 18816 + 6272 + 160 + 32 + 20*64 + 20*64 = 27840 fl.
// ---------------------------------------------------------------------------
__global__ void __launch_bounds__(640, 1) vitB(
    const float* __restrict__ WQ2,
    const float* __restrict__ WK2,
    const float* __restrict__ WV2,
    const float* __restrict__ f1w,
    const float* __restrict__ f1b,
    const float* __restrict__ f2w,
    const float* __restrict__ f2b,
    float* __restrict__ out)
{
    extern __shared__ float sm[];
    float* sW2 = sm;            // 3 * 6272, [w][s][i/4][d][4]
    float* sF1t = sm + 18816;   // 6272 : [d8][s][j]
    float* sF2 = sm + 25088;    // 160
    float* sB1 = sm + 25248;    // 16
    float* sB2 = sm + 25264;    // 16
    float* sKV = sm + 25280;    // 20 * 64
    float* sHB = sm + 26560;    // 20 * 64

    const int tid = threadIdx.x;
    {
        const float* Wg[3] = {WQ2, WK2, WV2};
        for (int w = 0; w < 3; ++w) {
            const float* G = Wg[w];
            float* dst = sW2 + w * 6272;
            for (int idx = tid; idx < 6272; idx += 640) {
                int s = idx >> 7, r = idx & 127, i = r >> 3, d = r & 7;
                dst[s * 128 + (i >> 2) * 32 + d * 4 + (i & 3)] = G[(s * 8 + d) * 16 + i];
            }
        }
        for (int idx = tid; idx < 6272; idx += 640) {
            int d = idx / 784, r = idx - d * 784, s = r >> 4, j = r & 15;
            sF1t[(d * 49 + s) * 16 + j] = f1w[j * 392 + s * 8 + d];
        }
        for (int idx = tid; idx < 160; idx += 640) {
            int j = idx / 10, c = idx - j * 10;
            sF2[idx] = f2w[c * 16 + j];
        }
        if (tid < 16) sB1[tid] = f1b[tid];
        if (tid < 10) sB2[tid] = f2b[tid];
    }
    __syncthreads();

    const int warpId = tid >> 5;
    const int lane = tid & 31;
    const int oct = lane >> 3;   // element within group
    const int d8 = lane & 7;     // output dim
    float* kb = sKV + warpId * 64;
    float* hb = sHB + warpId * 64;

    for (;;) {
        unsigned grp;
        if (lane == 0) grp = atomicAdd(&g_ctrB, 1u);
        grp = __shfl_sync(FULLMASK, grp, 0);
        if (grp >= 4096) break;
        const int elem = (int)grp * 4 + oct;
        const float* tb = g_tok2 + (size_t)elem * 784;
        float* vb = g_v2 + (size_t)elem * 392;
        const ulonglong2* pvu = (const ulonglong2*)tb;

        u64 Sp[4];
#pragma unroll
        for (int e = 0; e < 4; ++e) Sp[e] = 0ull;

        int cur = 0;
        ulonglong2 t0 = __ldg(pvu + 0), t1 = __ldg(pvu + 1);
        ulonglong2 t2 = __ldg(pvu + 2), t3 = __ldg(pvu + 3);
        u64 P0 = t0.x, P1 = t0.y, P2 = t1.x, P3 = t1.y;
        u64 P4 = t2.x, P5 = t2.y, P6 = t3.x, P7 = t3.y;

        // ---- pass 1: q2,k2,v2 per s; gram; store v2 ----
#pragma unroll 1
        for (int s = 0; s < 49; ++s) {
            int sn = (s < 48) ? s + 1 : 48;
            ulonglong2 n0 = __ldg(pvu + sn * 4 + 0), n1 = __ldg(pvu + sn * 4 + 1);
            ulonglong2 n2 = __ldg(pvu + sn * 4 + 2), n3 = __ldg(pvu + sn * 4 + 3);

            float q, k, v;
            PDOT(q, sW2 + s * 128 + d8 * 4, 4, 0.f);
            PDOT(k, sW2 + 6272 + s * 128 + d8 * 4, 4, 0.f);
            PDOT(v, sW2 + 12544 + s * 128 + d8 * 4, 4, 0.f);
            vb[s * 8 + d8] = v;

            kb[cur * 32 + lane] = k;
            __syncwarp();
            const ulonglong2* kq = (const ulonglong2*)(kb + cur * 32 + oct * 8);
            ulonglong2 K0 = kq[0], K1 = kq[1];
            u64 qp = pack2(q, q);
            Sp[0] = ffma2(qp, K0.x, Sp[0]); Sp[1] = ffma2(qp, K0.y, Sp[1]);
            Sp[2] = ffma2(qp, K1.x, Sp[2]); Sp[3] = ffma2(qp, K1.y, Sp[3]);
            cur ^= 1;
            P0 = n0.x; P1 = n0.y; P2 = n1.x; P3 = n1.y;
            P4 = n2.x; P5 = n2.y; P6 = n3.x; P7 = n3.y;
        }
        {
            u64 sv = pack2(1.f / 7.f, 1.f / 7.f);
#pragma unroll
            for (int e = 0; e < 4; ++e) Sp[e] = fmul2(Sp[e], sv);
        }

        __syncwarp();  // v2 stores visible warp-wide

        // ---- pass 2: read v2, apply S2, softmax(8), fc1 fused (packed) ----
        u64 Hp[8];
#pragma unroll
        for (int j = 0; j < 8; ++j) Hp[j] = 0ull;

        const ulonglong2* vvu = (const ulonglong2*)vb;
        ulonglong2 U0 = vvu[0], U1 = vvu[1];
#pragma unroll 1
        for (int s = 0; s < 49; ++s) {
            int sn = (s < 48) ? s + 1 : 48;
            ulonglong2 M0 = vvu[sn * 2 + 0], M1 = vvu[sn * 2 + 1];

            u64 a = 0ull, b = 0ull;
            a = ffma2(Sp[0], U0.x, a); b = ffma2(Sp[1], U0.y, b);
            a = ffma2(Sp[2], U1.x, a); b = ffma2(Sp[3], U1.y, b);
            float2 f = unpack2(fadd2(a, b));
            float o = f.x + f.y;

            float m = o;
#pragma unroll
            for (int dd = 4; dd; dd >>= 1)
                m = fmaxf(m, __shfl_xor_sync(FULLMASK, m, dd, 8));
            float ex = __expf(o - m);
            float sum = ex;
#pragma unroll
            for (int dd = 4; dd; dd >>= 1)
                sum += __shfl_xor_sync(FULLMASK, sum, dd, 8);
            float tv = __fdividef(ex, sum);   // tok3[s][d8]

            const ulonglong2* wt = (const ulonglong2*)(sF1t + (d8 * 49 + s) * 16);
            ulonglong2 W0 = wt[0], W1 = wt[1];
            u64 tvp = pack2(tv, tv);
            Hp[0] = ffma2(tvp, W0.x, Hp[0]); Hp[1] = ffma2(tvp, W0.y, Hp[1]);
            Hp[2] = ffma2(tvp, W1.x, Hp[2]); Hp[3] = ffma2(tvp, W1.y, Hp[3]);
            const ulonglong2* wt2 = wt + 2;
            ulonglong2 W2 = wt2[0], W3 = wt2[1];
            Hp[4] = ffma2(tvp, W2.x, Hp[4]); Hp[5] = ffma2(tvp, W2.y, Hp[5]);
            Hp[6] = ffma2(tvp, W3.x, Hp[6]); Hp[7] = ffma2(tvp, W3.y, Hp[7]);
            U0 = M0; U1 = M1;
        }

        float h[16];
#pragma unroll
        for (int j = 0; j < 8; ++j) {
            float2 f = unpack2(Hp[j]);
            h[2 * j] = f.x; h[2 * j + 1] = f.y;
        }

        // split-butterfly reduce over the 8 octet lanes: 14 shfl total
#pragma unroll
        for (int j = 0; j < 8; ++j) {
            float sendv = (d8 & 1) ? h[j] : h[j + 8];
            float keep  = (d8 & 1) ? h[j + 8] : h[j];
            h[j] = keep + __shfl_xor_sync(FULLMASK, sendv, 1, 8);
        }
#pragma unroll
        for (int j = 0; j < 4; ++j) {
            float sendv = (d8 & 2) ? h[j] : h[j + 4];
            float keep  = (d8 & 2) ? h[j + 4] : h[j];
            h[j] = keep + __shfl_xor_sync(FULLMASK, sendv, 2, 8);
        }
#pragma unroll
        for (int j = 0; j < 2; ++j) {
            float sendv = (d8 & 4) ? h[j] : h[j + 2];
            float keep  = (d8 & 4) ? h[j + 2] : h[j];
            h[j] = keep + __shfl_xor_sync(FULLMASK, sendv, 4, 8);
        }
        int ja = 8 * (d8 & 1) + 4 * ((d8 >> 1) & 1) + 2 * ((d8 >> 2) & 1);
        __syncwarp();
        hb[oct * 16 + ja] = fmaxf(h[0] + sB1[ja], 0.f);
        hb[oct * 16 + ja + 1] = fmaxf(h[1] + sB1[ja + 1], 0.f);
        __syncwarp();

        // ---- fc2 + softmax over 10 (octet-local) ----
        const float* ho = hb + oct * 16;
        int c2 = (d8 < 2) ? (d8 + 8) : 8;
        float lg1 = sB2[d8];
        float lg2 = sB2[c2];
#pragma unroll
        for (int j = 0; j < 16; ++j) {
            float hv = ho[j];
            lg1 = fmaf(hv, sF2[j * 10 + d8], lg1);
            lg2 = fmaf(hv, sF2[j * 10 + c2], lg2);
        }
        float lg2v = (d8 < 2) ? lg2 : -1e30f;
        float m = fmaxf(lg1, lg2v);
#pragma unroll
        for (int dd = 4; dd; dd >>= 1)
            m = fmaxf(m, __shfl_xor_sync(FULLMASK, m, dd, 8));
        float e1 = __expf(lg1 - m);
        float e2 = (d8 < 2) ? __expf(lg2 - m) : 0.f;
        float sum = e1 + e2;
#pragma unroll
        for (int dd = 4; dd; dd >>= 1)
            sum += __shfl_xor_sync(FULLMASK, sum, dd, 8);
        float inv = __fdividef(1.f, sum);
        out[elem * 10 + d8] = e1 * inv;
        if (d8 < 2) out[elem * 10 + 8 + d8] = e2 * inv;
        __syncwarp();  // protect hb before next iteration
    }
}

extern "C" void kernel_launch(void* const* d_in, const int* in_sizes, int n_in,
                              void* d_out, int out_size)
{
    (void)in_sizes; (void)n_in; (void)out_size;
    const float* x   = (const float*)d_in[0];
    const float* pe  = (const float*)d_in[1];
    const float* WQ1 = (const float*)d_in[2];
    const float* WK1 = (const float*)d_in[3];
    const float* WV1 = (const float*)d_in[4];
    const float* WQ2 = (const float*)d_in[5];
    const float* WK2 = (const float*)d_in[6];
    const float* WV2 = (const float*)d_in[7];
    const float* f1w = (const float*)d_in[8];
    const float* f1b = (const float*)d_in[9];
    const float* f2w = (const float*)d_in[10];
    const float* f2b = (const float*)d_in[11];
    float* out = (float*)d_out;

    const size_t smA = (size_t)41264 * sizeof(float);  // 165056 B
    const size_t smB = (size_t)27840 * sizeof(float);  // 111360 B
    cudaFuncSetAttribute(vitA, cudaFuncAttributeMaxDynamicSharedMemorySize, (int)smA);
    cudaFuncSetAttribute(vitB, cudaFuncAttributeMaxDynamicSharedMemorySize, (int)smB);

    vitP<<<(16384 * 196 + 255) / 256, 256>>>(x);
    vitA<<<148, 640, smA>>>(pe, WQ1, WK1, WV1);
    vitB<<<148, 640, smB>>>(WQ2, WK2, WV2, f1w, f1b, f2w, f2b, out);
}